// round 1
// baseline (speedup 1.0000x reference)
#include <cuda_runtime.h>
#include <cstdint>

#define LRELU_ALPHA 0.2f

typedef unsigned long long u64;

// packed f32x2 FMA: d.lo += ... (elementwise fma on 2 packed floats)
__device__ __forceinline__ void ffma2(u64 &d, u64 a, u64 b){
    asm("fma.rn.f32x2 %0, %1, %2, %0;" : "+l"(d) : "l"(a), "l"(b));
}
__device__ __forceinline__ float hsum2(u64 v){
    float lo, hi;
    asm("mov.b64 {%0,%1}, %2;" : "=f"(lo), "=f"(hi) : "l"(v));
    return lo + hi;
}

// ping-pong activation buffers (allocation-free scratch)
__device__ __align__(16) float g_bufA[67108864];   // 268 MB: h1, h3, d1, d3
__device__ __align__(16) float g_bufB[33554432];   // 134 MB: h2, q,  d2
__device__ __align__(16) float g_wT[151552];       // transposed weights

// transpose [3,3,CI,CO] (HWIO) -> [9][CO][CI]
__global__ void transpose_w_kernel(const float* __restrict__ w, float* __restrict__ wT,
                                   int CI, int CO){
    int i = blockIdx.x*blockDim.x + threadIdx.x;
    int T = 9*CI*CO;
    if (i >= T) return;
    int co = i % CO; int t = i / CO; int ci = t % CI; int kk = t / CI;
    wT[(kk*CO + co)*CI + ci] = w[i];
}

// Generic 3x3 conv / transposed-conv (phase-decomposed), NHWC fp32.
//  conv   stride S (SAME, pad_lo=0 for our stride-2 layers): DIL=1
//  deconv stride 2 (lhs_dilation=2, pad=(2,1)):              S=1, DIL=2, PAD=2
// Each thread: 1 cout x RP consecutive output columns.
template<int S, int DIL, int PAD, int CI, int CO, int RP, bool RELU>
__global__ __launch_bounds__(256) void conv_kernel(
    const float* __restrict__ in, const float* __restrict__ wT,
    const float* __restrict__ bias, float* __restrict__ out,
    int N, int Hin, int Win, int Hout, int Wout)
{
    constexpr int BLOCK = 256;
    constexpr int G = BLOCK / CO;
    static_assert(RP % 2 == 0, "RP must be even for compile-time phase folding");

    const int co = threadIdx.x % CO;
    const int g  = threadIdx.x / CO;
    const int w0 = (blockIdx.x * G + g) * RP;
    const int h  = blockIdx.y;
    const int n  = blockIdx.z;
    if (w0 >= Wout) return;

    u64   accA[RP], accB[RP];
    float accS[RP];
    #pragma unroll
    for (int r=0;r<RP;r++){ accA[r]=0ull; accB[r]=0ull; accS[r]=0.f; }

    #pragma unroll
    for (int ky=0; ky<3; ky++){
        int uy = h*S + ky - PAD;
        int ihy;
        if (DIL==2){ if (uy & 1) continue; ihy = uy >> 1; } else { ihy = uy; }
        if (ihy < 0 || ihy >= Hin) continue;
        const float* __restrict__ rowp = in + (size_t)(n*Hin + ihy) * Win * CI;

        #pragma unroll
        for (int kx=0; kx<3; kx++){
            const float* __restrict__ wp = wT + ((size_t)(ky*3+kx)*CO + co) * CI;
            int ofs[RP];
            bool v[RP];
            bool allv = true;
            #pragma unroll
            for (int r=0;r<RP;r++){
                // phase: for DIL=2, w0 is even, so parity folds at compile time
                bool phase = (DIL==1) || (((r + kx - PAD) & 1) == 0);
                int ux = (w0+r)*S + kx - PAD;
                int iw = (DIL==2) ? (ux >> 1) : ux;
                bool val = phase && (iw >= 0) && (iw < Win);
                v[r] = val;
                ofs[r] = val ? iw*CI : 0;
                if (phase) allv = allv && val;
            }

            if constexpr (CI % 4 == 0) {
                if (allv){
                    #pragma unroll 4
                    for (int ci=0; ci<CI; ci+=4){
                        ulonglong2 wv = *reinterpret_cast<const ulonglong2*>(wp + ci);
                        #pragma unroll
                        for (int r=0;r<RP;r++){
                            if ((DIL==1) || (((r + kx - PAD) & 1) == 0)){
                                ulonglong2 xv = *reinterpret_cast<const ulonglong2*>(rowp + ofs[r] + ci);
                                ffma2(accA[r], xv.x, wv.x);
                                ffma2(accB[r], xv.y, wv.y);
                            }
                        }
                    }
                } else {
                    #pragma unroll 4
                    for (int ci=0; ci<CI; ci+=4){
                        ulonglong2 wv = *reinterpret_cast<const ulonglong2*>(wp + ci);
                        #pragma unroll
                        for (int r=0;r<RP;r++){
                            if ((DIL==1) || (((r + kx - PAD) & 1) == 0)){
                                if (v[r]){
                                    ulonglong2 xv = *reinterpret_cast<const ulonglong2*>(rowp + ofs[r] + ci);
                                    ffma2(accA[r], xv.x, wv.x);
                                    ffma2(accB[r], xv.y, wv.y);
                                }
                            }
                        }
                    }
                }
            } else {
                // scalar fallback (enc1: CI=3)
                #pragma unroll
                for (int ci=0; ci<CI; ci++){
                    float wvs = wp[ci];
                    #pragma unroll
                    for (int r=0;r<RP;r++){
                        if ((DIL==1) || (((r + kx - PAD) & 1) == 0)){
                            float xv = v[r] ? rowp[ofs[r] + ci] : 0.f;
                            accS[r] += xv * wvs;
                        }
                    }
                }
            }
        }
    }

    const float bv = bias[co];
    const int ob = ((n*Hout + h)*Wout + w0)*CO + co;
    #pragma unroll
    for (int r=0;r<RP;r++){
        float o = hsum2(accA[r]) + hsum2(accB[r]) + accS[r] + bv;
        if (RELU) o = (o > 0.f) ? o : LRELU_ALPHA * o;
        out[ob + r*CO] = o;
    }
}

// fused enc4 (1x1 conv, 64->32) + vector quantization
// h3: [NP,64]; w: [64,32]; b: [32]; cb: [32,64]; q: [NP,32]
__global__ __launch_bounds__(256) void enc4_vq_kernel(
    const float* __restrict__ h3, const float* __restrict__ w,
    const float* __restrict__ b, const float* __restrict__ cb,
    float* __restrict__ q, int NP)
{
    int p = blockIdx.x*blockDim.x + threadIdx.x;
    if (p >= NP) return;
    float z[32];
    #pragma unroll
    for (int d=0;d<32;d++) z[d] = b[d];
    const float* hp = h3 + (size_t)p*64;
    #pragma unroll 4
    for (int ci=0;ci<64;ci++){
        float hv = hp[ci];
        #pragma unroll
        for (int d=0;d<32;d++) z[d] += hv * w[ci*32 + d];
    }
    // dist_k = ||e_k||^2 - 2 z.e_k  (||z||^2 constant per pixel, argmin-invariant)
    float best = 3.4e38f; int bk = 0;
    for (int k=0;k<64;k++){
        float dist = 0.f;
        #pragma unroll
        for (int d=0;d<32;d++){
            float e = cb[d*64 + k];
            dist += e*(e - 2.f*z[d]);
        }
        if (dist < best){ best = dist; bk = k; }   // strict < == first-min (jnp.argmin)
    }
    float* qp = q + (size_t)p*32;
    #pragma unroll
    for (int d=0;d<32;d++) qp[d] = cb[d*64 + bk];
}

// dec4: conv_transpose stride 1 (== SAME conv pad 1), CI=32, CO=1.
// warp handles 4 consecutive output columns; lanes span ci (coalesced loads).
__global__ __launch_bounds__(256) void dec4_kernel(
    const float* __restrict__ in, const float* __restrict__ w,
    const float* __restrict__ b, float* __restrict__ out,
    int N, int H, int W)
{
    int gw = (blockIdx.x * blockDim.x + threadIdx.x) >> 5;
    int lane = threadIdx.x & 31;
    int gpr = W >> 2;                 // pixel groups per row
    int total = N*H*gpr;
    if (gw >= total) return;
    int gx = gw % gpr; int t = gw / gpr;
    int h = t % H; int n = t / H;
    int w0 = gx*4;

    float wk[9];
    #pragma unroll
    for (int i=0;i<9;i++) wk[i] = w[i*32 + lane];

    float acc[4] = {0.f,0.f,0.f,0.f};
    #pragma unroll
    for (int ky=0;ky<3;ky++){
        int ih = h + ky - 1;
        if (ih < 0 || ih >= H) continue;
        const float* rowp = in + ((size_t)(n*H + ih)*W)*32 + lane;
        float v[6];
        #pragma unroll
        for (int c=0;c<6;c++){
            int iw = w0 - 1 + c;
            v[c] = (iw >= 0 && iw < W) ? rowp[(size_t)iw*32] : 0.f;
        }
        #pragma unroll
        for (int kx=0;kx<3;kx++)
            #pragma unroll
            for (int r=0;r<4;r++)
                acc[r] += v[r+kx] * wk[ky*3+kx];
    }
    float bv = b[0];
    #pragma unroll
    for (int r=0;r<4;r++){
        float a = acc[r];
        #pragma unroll
        for (int o=16;o;o>>=1) a += __shfl_xor_sync(0xffffffffu, a, o);
        if (lane == 0) out[((size_t)(n*H + h)*W) + w0 + r] = a + bv;
    }
}

extern "C" void kernel_launch(void* const* d_in, const int* in_sizes, int n_in,
                              void* d_out, int out_size)
{
    (void)in_sizes; (void)n_in; (void)out_size;
    const float* x   = (const float*)d_in[0];
    const float* e1w = (const float*)d_in[1];  const float* e1b = (const float*)d_in[2];
    const float* e2w = (const float*)d_in[3];  const float* e2b = (const float*)d_in[4];
    const float* e3w = (const float*)d_in[5];  const float* e3b = (const float*)d_in[6];
    const float* e4w = (const float*)d_in[7];  const float* e4b = (const float*)d_in[8];
    const float* cb  = (const float*)d_in[9];
    const float* d1w = (const float*)d_in[10]; const float* d1b = (const float*)d_in[11];
    const float* d2w = (const float*)d_in[12]; const float* d2b = (const float*)d_in[13];
    const float* d3w = (const float*)d_in[14]; const float* d3b = (const float*)d_in[15];
    const float* d4w = (const float*)d_in[16]; const float* d4b = (const float*)d_in[17];
    float* out = (float*)d_out;

    float *A, *B, *wT;
    cudaGetSymbolAddress((void**)&A,  g_bufA);
    cudaGetSymbolAddress((void**)&B,  g_bufB);
    cudaGetSymbolAddress((void**)&wT, g_wT);

    const int O_E1=0, O_E2=1024, O_E3=20480, O_D1=57344, O_D2=76800, O_D3=113664;

    transpose_w_kernel<<< (9*3*32 +255)/256, 256 >>>(e1w, wT+O_E1, 3, 32);
    transpose_w_kernel<<< (9*32*64+255)/256, 256 >>>(e2w, wT+O_E2, 32, 64);
    transpose_w_kernel<<< (9*64*64+255)/256, 256 >>>(e3w, wT+O_E3, 64, 64);
    transpose_w_kernel<<< (9*32*64+255)/256, 256 >>>(d1w, wT+O_D1, 32, 64);
    transpose_w_kernel<<< (9*64*64+255)/256, 256 >>>(d2w, wT+O_D2, 64, 64);
    transpose_w_kernel<<< (9*64*32+255)/256, 256 >>>(d3w, wT+O_D3, 64, 32);

    // encoder: 256 -> 128 -> 64 -> 32
    conv_kernel<2,1,0, 3,32,4,true ><<< dim3(128/32, 128, 32), 256 >>>(x, wT+O_E1, e1b, A, 32,256,256,128,128);
    conv_kernel<2,1,0,32,64,4,true ><<< dim3( 64/16,  64, 32), 256 >>>(A, wT+O_E2, e2b, B, 32,128,128, 64, 64);
    conv_kernel<2,1,0,64,64,4,true ><<< dim3( 32/16,  32, 32), 256 >>>(B, wT+O_E3, e3b, A, 32, 64, 64, 32, 32);

    // enc4 (1x1) + VQ fused
    enc4_vq_kernel<<< 32768/256, 256 >>>(A, e4w, e4b, cb, B, 32768);

    // decoder: 32 -> 64 -> 128 -> 256
    conv_kernel<1,2,2,32,64,4,true ><<< dim3( 64/16,  64, 32), 256 >>>(B, wT+O_D1, d1b, A, 32, 32, 32, 64, 64);
    conv_kernel<1,2,2,64,64,4,true ><<< dim3(128/16, 128, 32), 256 >>>(A, wT+O_D2, d2b, B, 32, 64, 64,128,128);
    conv_kernel<1,2,2,64,32,4,true ><<< dim3(256/32, 256, 32), 256 >>>(B, wT+O_D3, d3b, A, 32,128,128,256,256);

    // dec4: stride-1 deconv == SAME conv, CO=1
    dec4_kernel<<< 65536, 256 >>>(A, d4w, d4b, out, 32, 256, 256);
}

// round 2
// speedup vs baseline: 4.2846x; 4.2846x over previous
#include <cuda_runtime.h>
#include <cstdint>

#define LRELU_ALPHA 0.2f

typedef unsigned long long u64;

// packed f32x2 helpers (sm_103a FFMA2 is PTX-only)
__device__ __forceinline__ void ffma2(u64 &d, u64 a, u64 b){
    asm("fma.rn.f32x2 %0, %1, %2, %0;" : "+l"(d) : "l"(a), "l"(b));
}
__device__ __forceinline__ u64 pack2(float s){
    u64 d; asm("mov.b64 %0, {%1, %1};" : "=l"(d) : "f"(s)); return d;
}
__device__ __forceinline__ void fadd2(u64 &d, u64 a, u64 b){
    asm("add.rn.f32x2 %0, %1, %2;" : "=l"(d) : "l"(a), "l"(b));
}
__device__ __forceinline__ void unpack2(float &lo, float &hi, u64 v){
    asm("mov.b64 {%0,%1}, %2;" : "=f"(lo), "=f"(hi) : "l"(v));
}

// ping-pong activation buffers (allocation-free scratch)
__device__ __align__(16) float g_bufA[67108864];   // h1, h3, d1, d3
__device__ __align__(16) float g_bufB[33554432];   // h2, q,  d2

// ---------------------------------------------------------------------------
// 3x3 conv / transposed-conv, NHWC fp32, weights in ORIGINAL HWIO [9][CI][CO].
//   conv   stride S (SAME, pad_lo=0 for stride-2 layers): DIL=1, PAD=0
//   deconv stride 2 (lhs_dilation=2, pad=(2,1)):          S=1, DIL=2, PAD=2
// Thread = 1 co-PAIR (f32x2 over co) x RP consecutive output columns.
// Lane index carries cp -> weight LDG.64 and output ST.64 fully coalesced;
// x loads broadcast within the warp.
// ---------------------------------------------------------------------------
template<int S, int DIL, int PAD, int CI, int CO, int RP, bool RELU>
__global__ __launch_bounds__(256) void conv2_kernel(
    const float* __restrict__ in, const float* __restrict__ w,
    const float* __restrict__ bias, float* __restrict__ out,
    int N, int Hin, int Win, int Hout, int Wout)
{
    constexpr int CP = CO / 2;        // co-pairs
    constexpr int G  = 256 / CP;      // pixel groups per block
    static_assert(RP % 2 == 0, "RP even: compile-time phase folding needs even w0");

    const int cp = threadIdx.x % CP;
    const int g  = threadIdx.x / CP;
    const int w0 = (blockIdx.x * G + g) * RP;
    const int h  = blockIdx.y;
    const int n  = blockIdx.z;
    if (w0 >= Wout) return;

    u64 accA[RP], accB[RP];
    #pragma unroll
    for (int r=0;r<RP;r++){ accA[r]=0ull; accB[r]=0ull; }

    #pragma unroll
    for (int ky=0; ky<3; ky++){
        int uy = h*S + ky - PAD;
        int ihy;
        if (DIL==2){ if (uy & 1) continue; ihy = uy >> 1; } else { ihy = uy; }
        if (ihy < 0 || ihy >= Hin) continue;
        const float* __restrict__ rowp = in + (size_t)(n*Hin + ihy) * Win * CI;

        #pragma unroll
        for (int kx=0; kx<3; kx++){
            const float* __restrict__ wp = w + (size_t)((ky*3+kx)*CI) * CO + 2*cp;
            int  ofs[RP];
            bool v[RP];
            #pragma unroll
            for (int r=0;r<RP;r++){
                bool phase = (DIL==1) || (((r + kx - PAD) & 1) == 0);
                int ux = (w0+r)*S + kx - PAD;
                int iw = (DIL==2) ? (ux >> 1) : ux;
                v[r]   = phase && (iw >= 0) && (iw < Win);
                ofs[r] = v[r] ? iw*CI : 0;
            }

            if constexpr (CI % 4 == 0) {
                #pragma unroll 2
                for (int ci=0; ci<CI; ci+=4){
                    u64 wv0 = *reinterpret_cast<const u64*>(wp + (size_t)(ci+0)*CO);
                    u64 wv1 = *reinterpret_cast<const u64*>(wp + (size_t)(ci+1)*CO);
                    u64 wv2 = *reinterpret_cast<const u64*>(wp + (size_t)(ci+2)*CO);
                    u64 wv3 = *reinterpret_cast<const u64*>(wp + (size_t)(ci+3)*CO);
                    #pragma unroll
                    for (int r=0;r<RP;r++){
                        if ((DIL==1) || (((r + kx - PAD) & 1) == 0)){
                            if (v[r]){
                                float4 xv = *reinterpret_cast<const float4*>(rowp + ofs[r] + ci);
                                ffma2(accA[r], wv0, pack2(xv.x));
                                ffma2(accB[r], wv1, pack2(xv.y));
                                ffma2(accA[r], wv2, pack2(xv.z));
                                ffma2(accB[r], wv3, pack2(xv.w));
                            }
                        }
                    }
                }
            } else {
                // enc1: CI=3
                #pragma unroll
                for (int ci=0; ci<CI; ci++){
                    u64 wv = *reinterpret_cast<const u64*>(wp + (size_t)ci*CO);
                    #pragma unroll
                    for (int r=0;r<RP;r++){
                        if ((DIL==1) || (((r + kx - PAD) & 1) == 0)){
                            if (v[r]){
                                float xs = rowp[ofs[r] + ci];
                                ffma2(accA[r], wv, pack2(xs));
                            }
                        }
                    }
                }
            }
        }
    }

    const float2 bv = *reinterpret_cast<const float2*>(bias + 2*cp);
    const size_t ob = ((size_t)(n*Hout + h)*Wout + w0)*CO + 2*cp;
    #pragma unroll
    for (int r=0;r<RP;r++){
        u64 s; fadd2(s, accA[r], accB[r]);
        float lo, hi; unpack2(lo, hi, s);
        lo += bv.x; hi += bv.y;
        if (RELU){
            lo = (lo > 0.f) ? lo : LRELU_ALPHA * lo;
            hi = (hi > 0.f) ? hi : LRELU_ALPHA * hi;
        }
        float2 o; o.x = lo; o.y = hi;
        *reinterpret_cast<float2*>(out + ob + (size_t)r*CO) = o;
    }
}

// ---------------------------------------------------------------------------
// fused enc4 (1x1 conv, 64->32) + vector quantization
// h3: [NP,64]; w: [64,32]; b: [32]; cb: [32,64]; q: [NP,32]
// ---------------------------------------------------------------------------
__global__ __launch_bounds__(256) void enc4_vq_kernel(
    const float* __restrict__ h3, const float* __restrict__ w,
    const float* __restrict__ b, const float* __restrict__ cb,
    float* __restrict__ q, int NP)
{
    int p = blockIdx.x*blockDim.x + threadIdx.x;
    if (p >= NP) return;
    float z[32];
    #pragma unroll
    for (int d=0;d<32;d++) z[d] = b[d];
    const float* hp = h3 + (size_t)p*64;
    #pragma unroll 4
    for (int ci=0;ci<64;ci++){
        float hv = hp[ci];
        #pragma unroll
        for (int d=0;d<32;d++) z[d] += hv * w[ci*32 + d];
    }
    // dist_k = ||e_k||^2 - 2 z.e_k  (||z||^2 constant per pixel, argmin-invariant)
    float best = 3.4e38f; int bk = 0;
    for (int k=0;k<64;k++){
        float dist = 0.f;
        #pragma unroll
        for (int d=0;d<32;d++){
            float e = cb[d*64 + k];
            dist += e*(e - 2.f*z[d]);
        }
        if (dist < best){ best = dist; bk = k; }   // strict < == first-min (jnp.argmin)
    }
    float* qp = q + (size_t)p*32;
    #pragma unroll
    for (int d=0;d<32;d++) qp[d] = cb[d*64 + bk];
}

// ---------------------------------------------------------------------------
// dec4: conv_transpose stride 1 (== SAME conv pad 1), CI=32, CO=1.
// warp handles 4 consecutive output columns; lanes span ci (coalesced loads).
// ---------------------------------------------------------------------------
__global__ __launch_bounds__(256) void dec4_kernel(
    const float* __restrict__ in, const float* __restrict__ w,
    const float* __restrict__ b, float* __restrict__ out,
    int N, int H, int W)
{
    int gw = (blockIdx.x * blockDim.x + threadIdx.x) >> 5;
    int lane = threadIdx.x & 31;
    int gpr = W >> 2;                 // pixel groups per row
    int total = N*H*gpr;
    if (gw >= total) return;
    int gx = gw % gpr; int t = gw / gpr;
    int h = t % H; int n = t / H;
    int w0 = gx*4;

    float wk[9];
    #pragma unroll
    for (int i=0;i<9;i++) wk[i] = w[i*32 + lane];

    float acc[4] = {0.f,0.f,0.f,0.f};
    #pragma unroll
    for (int ky=0;ky<3;ky++){
        int ih = h + ky - 1;
        if (ih < 0 || ih >= H) continue;
        const float* rowp = in + ((size_t)(n*H + ih)*W)*32 + lane;
        float v[6];
        #pragma unroll
        for (int c=0;c<6;c++){
            int iw = w0 - 1 + c;
            v[c] = (iw >= 0 && iw < W) ? rowp[(size_t)iw*32] : 0.f;
        }
        #pragma unroll
        for (int kx=0;kx<3;kx++)
            #pragma unroll
            for (int r=0;r<4;r++)
                acc[r] += v[r+kx] * wk[ky*3+kx];
    }
    float bv = b[0];
    #pragma unroll
    for (int r=0;r<4;r++){
        float a = acc[r];
        #pragma unroll
        for (int o=16;o;o>>=1) a += __shfl_xor_sync(0xffffffffu, a, o);
        if (lane == 0) out[((size_t)(n*H + h)*W) + w0 + r] = a + bv;
    }
}

extern "C" void kernel_launch(void* const* d_in, const int* in_sizes, int n_in,
                              void* d_out, int out_size)
{
    (void)in_sizes; (void)n_in; (void)out_size;
    const float* x   = (const float*)d_in[0];
    const float* e1w = (const float*)d_in[1];  const float* e1b = (const float*)d_in[2];
    const float* e2w = (const float*)d_in[3];  const float* e2b = (const float*)d_in[4];
    const float* e3w = (const float*)d_in[5];  const float* e3b = (const float*)d_in[6];
    const float* e4w = (const float*)d_in[7];  const float* e4b = (const float*)d_in[8];
    const float* cb  = (const float*)d_in[9];
    const float* d1w = (const float*)d_in[10]; const float* d1b = (const float*)d_in[11];
    const float* d2w = (const float*)d_in[12]; const float* d2b = (const float*)d_in[13];
    const float* d3w = (const float*)d_in[14]; const float* d3b = (const float*)d_in[15];
    const float* d4w = (const float*)d_in[16]; const float* d4b = (const float*)d_in[17];
    float* out = (float*)d_out;

    float *A, *B;
    cudaGetSymbolAddress((void**)&A, g_bufA);
    cudaGetSymbolAddress((void**)&B, g_bufB);

    // encoder: 256 -> 128 -> 64 -> 32
    conv2_kernel<2,1,0, 3,32,8,true ><<< dim3(1,128,32), 256 >>>(x, e1w, e1b, A, 32,256,256,128,128);
    conv2_kernel<2,1,0,32,64,8,true ><<< dim3(1, 64,32), 256 >>>(A, e2w, e2b, B, 32,128,128, 64, 64);
    conv2_kernel<2,1,0,64,64,4,true ><<< dim3(1, 32,32), 256 >>>(B, e3w, e3b, A, 32, 64, 64, 32, 32);

    // enc4 (1x1) + VQ fused
    enc4_vq_kernel<<< 128, 256 >>>(A, e4w, e4b, cb, B, 32768);

    // decoder: 32 -> 64 -> 128 -> 256
    conv2_kernel<1,2,2,32,64,8,true ><<< dim3(1, 64,32), 256 >>>(B, d1w, d1b, A, 32, 32, 32, 64, 64);
    conv2_kernel<1,2,2,64,64,8,true ><<< dim3(2,128,32), 256 >>>(A, d2w, d2b, B, 32, 64, 64,128,128);
    conv2_kernel<1,2,2,64,32,8,true ><<< dim3(2,256,32), 256 >>>(B, d3w, d3b, A, 32,128,128,256,256);

    // dec4: stride-1 deconv == SAME conv, CO=1
    dec4_kernel<<< 65536, 256 >>>(A, d4w, d4b, out, 32, 256, 256);
}

// round 3
// speedup vs baseline: 5.4661x; 1.2758x over previous
#include <cuda_runtime.h>
#include <cstdint>

#define LRELU_ALPHA 0.2f

typedef unsigned long long u64;

// packed f32x2 helpers (sm_103a FFMA2 is PTX-only)
__device__ __forceinline__ void ffma2(u64 &d, u64 a, u64 b){
    asm("fma.rn.f32x2 %0, %1, %2, %0;" : "+l"(d) : "l"(a), "l"(b));
}
__device__ __forceinline__ u64 pack2(float s){
    u64 d; asm("mov.b64 %0, {%1, %1};" : "=l"(d) : "f"(s)); return d;
}
__device__ __forceinline__ void unpack2(float &lo, float &hi, u64 v){
    asm("mov.b64 {%0,%1}, %2;" : "=f"(lo), "=f"(hi) : "l"(v));
}

// ping-pong activation buffers (allocation-free scratch)
__device__ __align__(16) float g_bufA[67108864];   // h1, h3, d1, d3
__device__ __align__(16) float g_bufB[33554432];   // h2, q,  d2

// ---------------------------------------------------------------------------
// 3x3 conv / transposed-conv, NHWC fp32, weights in HWIO [9][CI][CO].
//   conv   stride S (SAME, pad_lo=0 for stride-2 layers): DIL=1, PAD=0
//   deconv stride 2 (lhs_dilation=2, pad=(2,1)):          S=1, DIL=2, PAD=2
// Thread = 4 consecutive couts (two f32x2 pairs, one LDG.128 per ci)
//          x RP consecutive output columns.
// cq on lane index -> w LDG.128 and out ST.128 coalesced (2 lines/warp);
// x LDG.128 broadcasts within a pixel-group.
// ---------------------------------------------------------------------------
template<int S, int DIL, int PAD, int CI, int CO, int RP, bool RELU>
__global__ __launch_bounds__(256) void conv4_kernel(
    const float* __restrict__ in, const float* __restrict__ w,
    const float* __restrict__ bias, float* __restrict__ out,
    int N, int Hin, int Win, int Hout, int Wout)
{
    constexpr int CQ = CO / 4;        // co-quads
    constexpr int G  = 256 / CQ;      // pixel groups per block
    static_assert(RP % 2 == 0, "RP even: compile-time phase folding needs even w0");

    const int cq = threadIdx.x % CQ;
    const int g  = threadIdx.x / CQ;
    const int w0 = (blockIdx.x * G + g) * RP;
    const int h  = blockIdx.y;
    const int n  = blockIdx.z;
    if (w0 >= Wout) return;

    u64 acc0[RP], acc1[RP];
    #pragma unroll
    for (int r=0;r<RP;r++){ acc0[r]=0ull; acc1[r]=0ull; }

    #pragma unroll
    for (int ky=0; ky<3; ky++){
        int uy = h*S + ky - PAD;
        int ihy;
        if (DIL==2){ if (uy & 1) continue; ihy = uy >> 1; } else { ihy = uy; }
        if (ihy < 0 || ihy >= Hin) continue;
        const float* __restrict__ rowp = in + (size_t)(n*Hin + ihy) * Win * CI;

        #pragma unroll
        for (int kx=0; kx<3; kx++){
            const float* __restrict__ wp = w + (size_t)((ky*3+kx)*CI) * CO + 4*cq;
            int  ofs[RP];
            bool v[RP];
            #pragma unroll
            for (int r=0;r<RP;r++){
                bool phase = (DIL==1) || (((r + kx - PAD) & 1) == 0);
                int ux = (w0+r)*S + kx - PAD;
                int iw = (DIL==2) ? (ux >> 1) : ux;
                v[r]   = phase && (iw >= 0) && (iw < Win);
                ofs[r] = v[r] ? iw*CI : 0;
            }

            if constexpr (CI % 4 == 0) {
                #pragma unroll 2
                for (int ci=0; ci<CI; ci+=4){
                    ulonglong2 wv0 = *reinterpret_cast<const ulonglong2*>(wp + (size_t)(ci+0)*CO);
                    ulonglong2 wv1 = *reinterpret_cast<const ulonglong2*>(wp + (size_t)(ci+1)*CO);
                    ulonglong2 wv2 = *reinterpret_cast<const ulonglong2*>(wp + (size_t)(ci+2)*CO);
                    ulonglong2 wv3 = *reinterpret_cast<const ulonglong2*>(wp + (size_t)(ci+3)*CO);
                    #pragma unroll
                    for (int r=0;r<RP;r++){
                        if ((DIL==1) || (((r + kx - PAD) & 1) == 0)){
                            if (v[r]){
                                float4 xv = *reinterpret_cast<const float4*>(rowp + ofs[r] + ci);
                                u64 p0 = pack2(xv.x), p1 = pack2(xv.y);
                                u64 p2 = pack2(xv.z), p3 = pack2(xv.w);
                                ffma2(acc0[r], wv0.x, p0); ffma2(acc1[r], wv0.y, p0);
                                ffma2(acc0[r], wv1.x, p1); ffma2(acc1[r], wv1.y, p1);
                                ffma2(acc0[r], wv2.x, p2); ffma2(acc1[r], wv2.y, p2);
                                ffma2(acc0[r], wv3.x, p3); ffma2(acc1[r], wv3.y, p3);
                            }
                        }
                    }
                }
            } else {
                // enc1: CI=3 (scalar x loads)
                #pragma unroll
                for (int ci=0; ci<CI; ci++){
                    ulonglong2 wv = *reinterpret_cast<const ulonglong2*>(wp + (size_t)ci*CO);
                    #pragma unroll
                    for (int r=0;r<RP;r++){
                        if ((DIL==1) || (((r + kx - PAD) & 1) == 0)){
                            if (v[r]){
                                u64 p = pack2(rowp[ofs[r] + ci]);
                                ffma2(acc0[r], wv.x, p);
                                ffma2(acc1[r], wv.y, p);
                            }
                        }
                    }
                }
            }
        }
    }

    const float4 bv = *reinterpret_cast<const float4*>(bias + 4*cq);
    const size_t ob = ((size_t)(n*Hout + h)*Wout + w0)*CO + 4*cq;
    #pragma unroll
    for (int r=0;r<RP;r++){
        float a0,a1,a2,a3;
        unpack2(a0,a1,acc0[r]); unpack2(a2,a3,acc1[r]);
        a0 += bv.x; a1 += bv.y; a2 += bv.z; a3 += bv.w;
        if (RELU){
            a0 = (a0 > 0.f) ? a0 : LRELU_ALPHA * a0;
            a1 = (a1 > 0.f) ? a1 : LRELU_ALPHA * a1;
            a2 = (a2 > 0.f) ? a2 : LRELU_ALPHA * a2;
            a3 = (a3 > 0.f) ? a3 : LRELU_ALPHA * a3;
        }
        float4 o; o.x=a0; o.y=a1; o.z=a2; o.w=a3;
        *reinterpret_cast<float4*>(out + ob + (size_t)r*CO) = o;
    }
}

// ---------------------------------------------------------------------------
// fused enc4 (1x1 conv, 64->32) + vector quantization
// h3: [NP,64]; w: [64,32]; b: [32]; cb: [32,64]; q: [NP,32]
// block=128 threads, 1 pixel/thread; w+cb staged in smem; no spills.
// ---------------------------------------------------------------------------
__global__ __launch_bounds__(128, 2) void enc4_vq_kernel(
    const float* __restrict__ h3, const float* __restrict__ w,
    const float* __restrict__ b, const float* __restrict__ cb,
    float* __restrict__ q, int NP)
{
    __shared__ float sw[2048];   // w  [64][32]
    __shared__ float scb[2048];  // cb [32][64]
    for (int i = threadIdx.x; i < 2048; i += 128){ sw[i] = w[i]; scb[i] = cb[i]; }
    __syncthreads();

    int p = blockIdx.x*blockDim.x + threadIdx.x;
    if (p >= NP) return;
    float z[32];
    #pragma unroll
    for (int d=0;d<32;d++) z[d] = b[d];
    const float* hp = h3 + (size_t)p*64;
    #pragma unroll
    for (int c4=0;c4<64;c4+=4){
        float4 hv = *reinterpret_cast<const float4*>(hp + c4);
        #pragma unroll
        for (int d=0;d<32;d++){
            z[d] += hv.x * sw[(c4+0)*32 + d];
            z[d] += hv.y * sw[(c4+1)*32 + d];
            z[d] += hv.z * sw[(c4+2)*32 + d];
            z[d] += hv.w * sw[(c4+3)*32 + d];
        }
    }
    // dist_k = ||e_k||^2 - 2 z.e_k  (||z||^2 constant per pixel, argmin-invariant)
    float best = 3.4e38f; int bk = 0;
    for (int k=0;k<64;k++){
        float dist = 0.f;
        #pragma unroll
        for (int d=0;d<32;d++){
            float e = scb[d*64 + k];
            dist += e*(e - 2.f*z[d]);
        }
        if (dist < best){ best = dist; bk = k; }   // strict < == first-min (jnp.argmin)
    }
    float* qp = q + (size_t)p*32;
    #pragma unroll
    for (int d=0;d<32;d++) qp[d] = scb[d*64 + bk];
}

// ---------------------------------------------------------------------------
// dec4: conv_transpose stride 1 (== SAME conv pad 1), CI=32, CO=1.
// warp handles 4 consecutive output columns; lanes span ci (coalesced loads).
// ---------------------------------------------------------------------------
__global__ __launch_bounds__(256) void dec4_kernel(
    const float* __restrict__ in, const float* __restrict__ w,
    const float* __restrict__ b, float* __restrict__ out,
    int N, int H, int W)
{
    int gw = (blockIdx.x * blockDim.x + threadIdx.x) >> 5;
    int lane = threadIdx.x & 31;
    int gpr = W >> 2;                 // pixel groups per row
    int total = N*H*gpr;
    if (gw >= total) return;
    int gx = gw % gpr; int t = gw / gpr;
    int h = t % H; int n = t / H;
    int w0 = gx*4;

    float wk[9];
    #pragma unroll
    for (int i=0;i<9;i++) wk[i] = w[i*32 + lane];

    float acc[4] = {0.f,0.f,0.f,0.f};
    #pragma unroll
    for (int ky=0;ky<3;ky++){
        int ih = h + ky - 1;
        if (ih < 0 || ih >= H) continue;
        const float* rowp = in + ((size_t)(n*H + ih)*W)*32 + lane;
        float v[6];
        #pragma unroll
        for (int c=0;c<6;c++){
            int iw = w0 - 1 + c;
            v[c] = (iw >= 0 && iw < W) ? rowp[(size_t)iw*32] : 0.f;
        }
        #pragma unroll
        for (int kx=0;kx<3;kx++)
            #pragma unroll
            for (int r=0;r<4;r++)
                acc[r] += v[r+kx] * wk[ky*3+kx];
    }
    float bv = b[0];
    #pragma unroll
    for (int r=0;r<4;r++){
        float a = acc[r];
        #pragma unroll
        for (int o=16;o;o>>=1) a += __shfl_xor_sync(0xffffffffu, a, o);
        if (lane == 0) out[((size_t)(n*H + h)*W) + w0 + r] = a + bv;
    }
}

extern "C" void kernel_launch(void* const* d_in, const int* in_sizes, int n_in,
                              void* d_out, int out_size)
{
    (void)in_sizes; (void)n_in; (void)out_size;
    const float* x   = (const float*)d_in[0];
    const float* e1w = (const float*)d_in[1];  const float* e1b = (const float*)d_in[2];
    const float* e2w = (const float*)d_in[3];  const float* e2b = (const float*)d_in[4];
    const float* e3w = (const float*)d_in[5];  const float* e3b = (const float*)d_in[6];
    const float* e4w = (const float*)d_in[7];  const float* e4b = (const float*)d_in[8];
    const float* cb  = (const float*)d_in[9];
    const float* d1w = (const float*)d_in[10]; const float* d1b = (const float*)d_in[11];
    const float* d2w = (const float*)d_in[12]; const float* d2b = (const float*)d_in[13];
    const float* d3w = (const float*)d_in[14]; const float* d3b = (const float*)d_in[15];
    const float* d4w = (const float*)d_in[16]; const float* d4b = (const float*)d_in[17];
    float* out = (float*)d_out;

    float *A, *B;
    cudaGetSymbolAddress((void**)&A, g_bufA);
    cudaGetSymbolAddress((void**)&B, g_bufB);

    // encoder: 256 -> 128 -> 64 -> 32
    conv4_kernel<2,1,0, 3,32,4,true ><<< dim3(1,128,32), 256 >>>(x, e1w, e1b, A, 32,256,256,128,128);
    conv4_kernel<2,1,0,32,64,4,true ><<< dim3(1, 64,32), 256 >>>(A, e2w, e2b, B, 32,128,128, 64, 64);
    conv4_kernel<2,1,0,64,64,2,true ><<< dim3(1, 32,32), 256 >>>(B, e3w, e3b, A, 32, 64, 64, 32, 32);

    // enc4 (1x1) + VQ fused
    enc4_vq_kernel<<< 256, 128 >>>(A, e4w, e4b, cb, B, 32768);

    // decoder: 32 -> 64 -> 128 -> 256
    conv4_kernel<1,2,2,32,64,4,true ><<< dim3(1, 64,32), 256 >>>(B, d1w, d1b, A, 32, 32, 32, 64, 64);
    conv4_kernel<1,2,2,64,64,8,true ><<< dim3(1,128,32), 256 >>>(A, d2w, d2b, B, 32, 64, 64,128,128);
    conv4_kernel<1,2,2,64,32,8,true ><<< dim3(1,256,32), 256 >>>(B, d3w, d3b, A, 32,128,128,256,256);

    // dec4: stride-1 deconv == SAME conv, CO=1
    dec4_kernel<<< 65536, 256 >>>(A, d4w, d4b, out, 32, 256, 256);
}